// round 1
// baseline (speedup 1.0000x reference)
#include <cuda_runtime.h>
#include <cuda_bf16.h>
#include <cstdint>

#define OUT_F 2048
#define IN_F  2048
#define NNZ   209715

// 16 MB scratch for the reconstructed dense weight, [OUT_F][IN_F] row-major.
__device__ float g_W[OUT_F * IN_F];

// ---------------------------------------------------------------------------
// Kernel 1: dequantize packed int4 -> fp32 weights.
// packed[o][j] holds two offset-by-8 codes: low nibble -> col 2j, high -> 2j+1.
// One thread per packed byte => one float2 store, fully coalesced.
// ---------------------------------------------------------------------------
__global__ void dequant_kernel(const int* __restrict__ packed,
                               const float* __restrict__ scales) {
    int idx = blockIdx.x * blockDim.x + threadIdx.x;   // over OUT_F * IN_F/2
    if (idx >= OUT_F * (IN_F / 2)) return;
    int o = idx >> 10;                                  // idx / (IN_F/2)
    int v = packed[idx];
    float s = scales[o];
    float2 w;
    w.x = (float)((v & 0xF) - 8) * s;
    w.y = (float)(((v >> 4) & 0xF) - 8) * s;
    reinterpret_cast<float2*>(g_W)[idx] = w;
}

// ---------------------------------------------------------------------------
// Kernel 2: scatter-add sparse COO residual into g_W (duplicates possible ->
// atomicAdd, matching JAX .at[].add semantics).
// ---------------------------------------------------------------------------
__global__ void scatter_kernel(const float* __restrict__ vals,
                               const int* __restrict__ rows,
                               const int* __restrict__ cols) {
    int i = blockIdx.x * blockDim.x + threadIdx.x;
    if (i >= NNZ) return;
    atomicAdd(&g_W[(size_t)rows[i] * IN_F + cols[i]], vals[i]);
}

// ---------------------------------------------------------------------------
// Kernel 3: C[T, OUT_F] = X[T, IN_F] @ W[OUT_F, IN_F]^T   (both K-contiguous)
// 128x128 block tile, BK=16, 8x8 per thread, 256 threads.
// Smem rows padded to 132 floats (16B-aligned rows, reduced store conflicts).
// ---------------------------------------------------------------------------
__global__ __launch_bounds__(256, 2)
void sgemm_nt(const float* __restrict__ X, float* __restrict__ C, int T) {
    __shared__ float As[16][132];   // As[k][m]
    __shared__ float Bs[16][132];   // Bs[k][n]

    const int n0 = blockIdx.x * 128;
    const int m0 = blockIdx.y * 128;
    const int tid = threadIdx.x;

    const int tCol = tid & 15;      // 0..15 -> 8 output cols each
    const int tRow = tid >> 4;      // 0..15 -> 8 output rows each

    const int lrow = tid >> 2;          // 0..63 (global-load row within tile)
    const int lcol = (tid & 3) << 2;    // 0,4,8,12 (k offset of float4)

    float acc[8][8];
    #pragma unroll
    for (int i = 0; i < 8; i++)
        #pragma unroll
        for (int j = 0; j < 8; j++) acc[i][j] = 0.0f;

    const float* Xp = X   + (size_t)(m0 + lrow) * IN_F + lcol;
    const float* Wp = g_W + (size_t)(n0 + lrow) * IN_F + lcol;

    for (int k0 = 0; k0 < IN_F; k0 += 16) {
        float4 a0 = *reinterpret_cast<const float4*>(Xp + k0);
        float4 a1 = *reinterpret_cast<const float4*>(Xp + (size_t)64 * IN_F + k0);
        float4 b0 = *reinterpret_cast<const float4*>(Wp + k0);
        float4 b1 = *reinterpret_cast<const float4*>(Wp + (size_t)64 * IN_F + k0);

        As[lcol + 0][lrow]      = a0.x;
        As[lcol + 1][lrow]      = a0.y;
        As[lcol + 2][lrow]      = a0.z;
        As[lcol + 3][lrow]      = a0.w;
        As[lcol + 0][lrow + 64] = a1.x;
        As[lcol + 1][lrow + 64] = a1.y;
        As[lcol + 2][lrow + 64] = a1.z;
        As[lcol + 3][lrow + 64] = a1.w;

        Bs[lcol + 0][lrow]      = b0.x;
        Bs[lcol + 1][lrow]      = b0.y;
        Bs[lcol + 2][lrow]      = b0.z;
        Bs[lcol + 3][lrow]      = b0.w;
        Bs[lcol + 0][lrow + 64] = b1.x;
        Bs[lcol + 1][lrow + 64] = b1.y;
        Bs[lcol + 2][lrow + 64] = b1.z;
        Bs[lcol + 3][lrow + 64] = b1.w;

        __syncthreads();

        #pragma unroll
        for (int k = 0; k < 16; k++) {
            float rm[8], rn[8];
            float4 m0v = *reinterpret_cast<const float4*>(&As[k][tRow * 8]);
            float4 m1v = *reinterpret_cast<const float4*>(&As[k][tRow * 8 + 4]);
            float4 n0v = *reinterpret_cast<const float4*>(&Bs[k][tCol * 8]);
            float4 n1v = *reinterpret_cast<const float4*>(&Bs[k][tCol * 8 + 4]);
            rm[0] = m0v.x; rm[1] = m0v.y; rm[2] = m0v.z; rm[3] = m0v.w;
            rm[4] = m1v.x; rm[5] = m1v.y; rm[6] = m1v.z; rm[7] = m1v.w;
            rn[0] = n0v.x; rn[1] = n0v.y; rn[2] = n0v.z; rn[3] = n0v.w;
            rn[4] = n1v.x; rn[5] = n1v.y; rn[6] = n1v.z; rn[7] = n1v.w;

            #pragma unroll
            for (int i = 0; i < 8; i++)
                #pragma unroll
                for (int j = 0; j < 8; j++)
                    acc[i][j] += rm[i] * rn[j];
        }

        __syncthreads();
    }

    #pragma unroll
    for (int i = 0; i < 8; i++) {
        float4* cp = reinterpret_cast<float4*>(
            C + (size_t)(m0 + tRow * 8 + i) * OUT_F + n0 + tCol * 8);
        cp[0] = make_float4(acc[i][0], acc[i][1], acc[i][2], acc[i][3]);
        cp[1] = make_float4(acc[i][4], acc[i][5], acc[i][6], acc[i][7]);
    }
}

// ---------------------------------------------------------------------------
// Launch: dequant -> scatter -> GEMM (same stream, implicit ordering).
// ---------------------------------------------------------------------------
extern "C" void kernel_launch(void* const* d_in, const int* in_sizes, int n_in,
                              void* d_out, int out_size) {
    const float* x        = (const float*)d_in[0];
    const int*   packed   = (const int*)  d_in[1];
    const float* scales   = (const float*)d_in[2];
    const float* o_vals   = (const float*)d_in[3];
    const int*   o_rows   = (const int*)  d_in[4];
    const int*   o_cols   = (const int*)  d_in[5];
    float*       out      = (float*)d_out;

    const int T = in_sizes[0] / IN_F;   // 16384 tokens

    {
        int n = OUT_F * (IN_F / 2);
        dequant_kernel<<<(n + 255) / 256, 256>>>(packed, scales);
    }
    {
        scatter_kernel<<<(NNZ + 255) / 256, 256>>>(o_vals, o_rows, o_cols);
    }
    {
        dim3 grid(OUT_F / 128, T / 128);
        sgemm_nt<<<grid, 256>>>(x, out, T);
    }
}

// round 3
// speedup vs baseline: 7.7837x; 7.7837x over previous
#include <cuda_runtime.h>
#include <cuda_fp16.h>
#include <cstdint>

#define OUT_F 2048
#define IN_F  2048
#define NNZ   209715
#define T_TOK 16384

// ---------------------------------------------------------------------------
// Scratch: fp16 copies of X and reconstructed W.
// ---------------------------------------------------------------------------
__device__ __half g_Wh[OUT_F * IN_F];           //  8 MB
__device__ __half g_Xh[(size_t)T_TOK * IN_F];   // 64 MB

__device__ __forceinline__ uint32_t smem_u32(const void* p) {
    uint32_t a;
    asm("{ .reg .u64 t; cvta.to.shared.u64 t, %1; cvt.u32.u64 %0, t; }"
        : "=r"(a) : "l"(p));
    return a;
}

// cp.async (sm_80 baseline — compiles for sm_103)
#define CP_ASYNC16(dst, src) \
    asm volatile("cp.async.cg.shared.global [%0], [%1], 16;" \
                 :: "r"((uint32_t)(dst)), "l"(src) : "memory")
#define CP_COMMIT() asm volatile("cp.async.commit_group;" ::: "memory")
#define CP_WAIT1()  asm volatile("cp.async.wait_group 1;" ::: "memory")
#define CP_WAIT0()  asm volatile("cp.async.wait_group 0;" ::: "memory")

// SW128 swizzle on byte offsets (128B rows, 1024B atoms)
#define SWZ(o) ((o) ^ (((o) >> 3) & 0x70))

__device__ __forceinline__ void ldmatrix_x4(uint32_t* r, uint32_t addr) {
    asm volatile("ldmatrix.sync.aligned.m8n8.x4.shared.b16 {%0,%1,%2,%3}, [%4];"
                 : "=r"(r[0]), "=r"(r[1]), "=r"(r[2]), "=r"(r[3]) : "r"(addr));
}

__device__ __forceinline__ void mma_16816(float* c, const uint32_t* a,
                                          const uint32_t* b) {
    asm volatile(
        "mma.sync.aligned.m16n8k16.row.col.f32.f16.f16.f32 "
        "{%0,%1,%2,%3}, {%4,%5,%6,%7}, {%8,%9}, {%0,%1,%2,%3};"
        : "+f"(c[0]), "+f"(c[1]), "+f"(c[2]), "+f"(c[3])
        : "r"(a[0]), "r"(a[1]), "r"(a[2]), "r"(a[3]), "r"(b[0]), "r"(b[1]));
}

// ---------------------------------------------------------------------------
// Kernel 1: dequantize packed int4 -> fp16 W.
// ---------------------------------------------------------------------------
__global__ void dequant_kernel(const int* __restrict__ packed,
                               const float* __restrict__ scales) {
    int idx = blockIdx.x * blockDim.x + threadIdx.x;
    if (idx >= OUT_F * (IN_F / 2)) return;
    int o = idx >> 10;                       // / (IN_F/2)
    int v = packed[idx];
    float s = scales[o];
    __half2 h = __floats2half2_rn((float)((v & 0xF) - 8) * s,
                                  (float)(((v >> 4) & 0xF) - 8) * s);
    reinterpret_cast<__half2*>(g_Wh)[idx] = h;
}

// ---------------------------------------------------------------------------
// Kernel 2: scatter-add COO residual into fp16 W.
// ---------------------------------------------------------------------------
__global__ void scatter_kernel(const float* __restrict__ vals,
                               const int* __restrict__ rows,
                               const int* __restrict__ cols) {
    int i = blockIdx.x * blockDim.x + threadIdx.x;
    if (i >= NNZ) return;
    atomicAdd(&g_Wh[(size_t)rows[i] * IN_F + cols[i]], __float2half(vals[i]));
}

// ---------------------------------------------------------------------------
// Kernel 3: convert X fp32 -> fp16.
// ---------------------------------------------------------------------------
__global__ void cvtx_kernel(const float* __restrict__ x) {
    int i = blockIdx.x * blockDim.x + threadIdx.x;
    if (i >= (T_TOK * IN_F) / 4) return;
    float4 v = reinterpret_cast<const float4*>(x)[i];
    reinterpret_cast<__half2*>(g_Xh)[2 * i]     = __floats2half2_rn(v.x, v.y);
    reinterpret_cast<__half2*>(g_Xh)[2 * i + 1] = __floats2half2_rn(v.z, v.w);
}

// ---------------------------------------------------------------------------
// Kernel 4: fp16 tensor-core GEMM via mma.sync (HMMA).
// C[T, OUT_F] = Xh @ Wh^T, fp32 accumulate.
// CTA tile 128x128, BK=64, 2-stage cp.async pipeline, 8 warps (64x32 each).
// ---------------------------------------------------------------------------
#define MT 128
#define NT 128
#define BK 64
#define STAGE_BYTES 32768u
#define A_OFF(s) ((s) * STAGE_BYTES)
#define B_OFF(s) (A_OFF(s) + 16384u)
#define GEMM_SMEM (2 * STAGE_BYTES)

__device__ __forceinline__ void load_stage(uint32_t sb, int tid,
                                           const __half* Xb, const __half* Wb,
                                           int k0, int s) {
    // A: 128 rows x 8 chunks(16B) = 1024 chunks
    #pragma unroll
    for (int j = 0; j < 4; j++) {
        int item = tid + j * 256;
        int row = item >> 3, ck = item & 7;
        CP_ASYNC16(sb + A_OFF(s) + SWZ(row * 128 + ck * 16),
                   Xb + (size_t)row * IN_F + k0 + ck * 8);
    }
    // B: same shape
    #pragma unroll
    for (int j = 0; j < 4; j++) {
        int item = tid + j * 256;
        int row = item >> 3, ck = item & 7;
        CP_ASYNC16(sb + B_OFF(s) + SWZ(row * 128 + ck * 16),
                   Wb + (size_t)row * IN_F + k0 + ck * 8);
    }
    CP_COMMIT();
}

__global__ __launch_bounds__(256) void gemm_hmma(float* __restrict__ C) {
    extern __shared__ char smem[];
    const uint32_t sb = smem_u32(smem);
    const int tid  = threadIdx.x;
    const int wid  = tid >> 5;
    const int lane = tid & 31;

    const int m0 = blockIdx.y * MT;
    const int n0 = blockIdx.x * NT;
    const int wm = (wid & 1) * 64;     // warp m offset in CTA tile
    const int wn = (wid >> 1) * 32;    // warp n offset

    const __half* Xb = g_Xh + (size_t)m0 * IN_F;
    const __half* Wb = g_Wh + (size_t)n0 * IN_F;

    float acc[4][4][4];
    #pragma unroll
    for (int i = 0; i < 4; i++)
        #pragma unroll
        for (int j = 0; j < 4; j++)
            #pragma unroll
            for (int q = 0; q < 4; q++) acc[i][j][q] = 0.0f;

    load_stage(sb, tid, Xb, Wb, 0, 0);

    const int NIT = IN_F / BK;   // 32
    for (int k = 0; k < NIT; k++) {
        if (k + 1 < NIT) {
            load_stage(sb, tid, Xb, Wb, (k + 1) * BK, (k + 1) & 1);
            CP_WAIT1();
        } else {
            CP_WAIT0();
        }
        __syncthreads();

        const uint32_t sA = sb + A_OFF(k & 1);
        const uint32_t sB = sb + B_OFF(k & 1);

        #pragma unroll
        for (int kk = 0; kk < BK; kk += 16) {
            // A fragments: 4 m-tiles of 16x16
            uint32_t af[4][4];
            #pragma unroll
            for (int mt = 0; mt < 4; mt++) {
                int row = wm + mt * 16 + (lane & 7) + ((lane >> 3) & 1) * 8;
                int ck  = (kk >> 3) + ((lane >> 4) & 1);
                ldmatrix_x4(af[mt], sA + SWZ(row * 128 + ck * 16));
            }
            // B fragments: 4 n-tiles of 16(k)x8(n), loaded as 2 x4 ldmatrix
            uint32_t bf[4][2];
            #pragma unroll
            for (int np = 0; np < 2; np++) {
                int sel = lane >> 3;                       // 0..3
                int row = wn + np * 16 + (sel >> 1) * 8 + (lane & 7);
                int ck  = (kk >> 3) + (sel & 1);
                uint32_t r[4];
                ldmatrix_x4(r, sB + SWZ(row * 128 + ck * 16));
                bf[np * 2 + 0][0] = r[0]; bf[np * 2 + 0][1] = r[1];
                bf[np * 2 + 1][0] = r[2]; bf[np * 2 + 1][1] = r[3];
            }
            #pragma unroll
            for (int mt = 0; mt < 4; mt++)
                #pragma unroll
                for (int nt = 0; nt < 4; nt++)
                    mma_16816(acc[mt][nt], af[mt], bf[nt]);
        }
        __syncthreads();
    }

    // Epilogue: acc fragment (c0,c1)=(m, n..n+1), (c2,c3)=(m+8, n..n+1)
    #pragma unroll
    for (int mt = 0; mt < 4; mt++) {
        #pragma unroll
        for (int nt = 0; nt < 4; nt++) {
            int m = m0 + wm + mt * 16 + (lane >> 2);
            int n = n0 + wn + nt * 8 + (lane & 3) * 2;
            float2* p0 = reinterpret_cast<float2*>(C + (size_t)m * OUT_F + n);
            float2* p1 = reinterpret_cast<float2*>(C + (size_t)(m + 8) * OUT_F + n);
            *p0 = make_float2(acc[mt][nt][0], acc[mt][nt][1]);
            *p1 = make_float2(acc[mt][nt][2], acc[mt][nt][3]);
        }
    }
}

// ---------------------------------------------------------------------------
// Launch
// ---------------------------------------------------------------------------
extern "C" void kernel_launch(void* const* d_in, const int* in_sizes, int n_in,
                              void* d_out, int out_size) {
    const float* x      = (const float*)d_in[0];
    const int*   packed = (const int*)  d_in[1];
    const float* scales = (const float*)d_in[2];
    const float* o_vals = (const float*)d_in[3];
    const int*   o_rows = (const int*)  d_in[4];
    const int*   o_cols = (const int*)  d_in[5];
    float*       out    = (float*)d_out;

    cudaFuncSetAttribute(gemm_hmma,
                         cudaFuncAttributeMaxDynamicSharedMemorySize, GEMM_SMEM);

    {
        int n = OUT_F * (IN_F / 2);
        dequant_kernel<<<(n + 255) / 256, 256>>>(packed, scales);
    }
    scatter_kernel<<<(NNZ + 255) / 256, 256>>>(o_vals, o_rows, o_cols);
    {
        int n = (T_TOK * IN_F) / 4;
        cvtx_kernel<<<(n + 255) / 256, 256>>>(x);
    }
    {
        dim3 grid(OUT_F / NT, T_TOK / MT);   // (16, 128)
        gemm_hmma<<<grid, 256, GEMM_SMEM>>>(out);
    }
}